// round 7
// baseline (speedup 1.0000x reference)
#include <cuda_runtime.h>
#include <cstdint>

// HIRNN (GR4J-style) forward, R6: TWO independent batch rows per thread.
// R3/R5 showed the single-chain version is exposed-latency bound (~100
// cyc/step vs ~40-cycle chain, ~36-cycle issue floor): the warp has nothing
// to issue while the u-chain waits. With 2 independent rows per thread the
// two chains hide each other's latency; per-step cost drops toward the
// fma-issue floor. 64 warps instead of 128 (latency-bound; SM count idle
// anyway).
//
// Step identities (exact away from <=1e-6 heaviside ties):
//  - heaviside select pairs == min/max
//  - GW >= 0 by induction  =>  BAS = RecK*GW,  GW' = (1-RecK)*GW + RECn
//  - max(s-1,0) == s - min(s,1); min(s,1) feeds the u-clamp
//  - q = SUB*w + (INR-RMO) + RecK*GW as a 3-FFMA chain
//  - clip(+-1e5) provably inactive; state normalized u = SMS/SMSC in [0,1]
//
// Q[t] (t>=1) uses the pre-step state at t  -> computed inside the loop.
// Q[0] uses the FINAL state (roll shift=1)  -> recomputed after the loop.

__device__ __forceinline__ float ex2f(float x) {
    float y;
    asm("ex2.approx.f32 %0, %1;" : "=f"(y) : "f"(x));
    return y;
}

struct Params {
    float INSC, SMSC, SUB, CRAK, RecK, alpha, ivS, ck2, lC, nSUB, nCRbi;
};

// One step: advances (u, GW); returns Q computed from the PRE-step state.
__device__ __forceinline__ float stepq(float Prec, float PET,
                                       float& u, float& GW, const Params& p)
{
    float INTm = fminf(PET, Prec);
    float INT  = fminf(p.INSC, INTm);
    float INR  = Prec - INT;
    float POT  = PET - INT;

    // critical chain: FFMA -> MUFU -> FMNMX -> FFMA(s) -> clamp
    float arg = fmaf(p.ck2, u, p.lC);
    float cap = ex2f(arg);                // COEFF * exp(-SQ*u)
    float RMO = fminf(cap, INR);

    // off-chain state polynomials (overlap with MUFU)
    float t10  = u * 10.0f;
    float m    = fminf(t10, POT);
    float base = fmaf(-p.ivS, m, u);      // u - ETS/SMSC
    float a    = fmaf(p.nSUB,  u, 1.0f);  // 1 - SUB*u
    float bi   = fmaf(p.nCRbi, u, p.ivS); // (1 - CRAK*u)/SMSC
    float fi   = a * bi;
    float w    = u * RMO;

    float s    = fmaf(RMO, fi, base);     // pre-clamp next u
    float umid = fminf(s, 1.0f);
    float u_n  = fmaxf(umid, 0.0f);
    float ov   = s - umid;                // == max(s-1,0)

    float cw   = p.CRAK * w;
    float REC  = cw * a;
    float RECn = fmaf(p.SMSC, ov, REC);
    float dq   = INR - RMO;
    float t1   = fmaf(p.RecK, GW, dq);    // IRUN + BAS
    float q    = fmaf(p.SUB,  w,  t1);    // + SRUN

    GW = fmaf(p.alpha, GW, RECn);         // (1-RecK)*GW + RECn
    u  = u_n;
    return q;
}

template <int T>
__global__ __launch_bounds__(32, 1)
void hirnn_kernel(const float* __restrict__ in,
                  const float* __restrict__ pINSC,
                  const float* __restrict__ pCOEFF,
                  const float* __restrict__ pSQ,
                  const float* __restrict__ pSMSC,
                  const float* __restrict__ pSUB,
                  const float* __restrict__ pCRAK,
                  const float* __restrict__ pRecK,
                  float* __restrict__ out, int B)
{
    int half = B >> 1;
    int ba = blockIdx.x * 32 + threadIdx.x;   // row A
    if (ba >= half) return;
    int bb = ba + half;                       // row B (independent chain)

    Params p;
    p.INSC   = fminf(fmaxf(pINSC[0]  * 5.f,   0.5f),   5.f);
    float CO = fminf(fmaxf(pCOEFF[0] * 400.f, 50.f),   400.f);
    float SQ = fminf(fmaxf(pSQ[0]    * 6.f,   0.f),    6.f);
    p.SMSC   = fminf(fmaxf(pSMSC[0]  * 500.f, 50.f),   500.f);
    p.SUB    = fminf(fmaxf(pSUB[0],           0.f),    1.f);
    p.CRAK   = fminf(fmaxf(pCRAK[0],          0.f),    1.f);
    p.RecK   = fminf(fmaxf(pRecK[0]  * 0.3f,  0.003f), 0.3f);
    p.alpha  = 1.f - p.RecK;
    p.ivS    = 1.f / p.SMSC;
    p.ck2    = -SQ * 1.44269504088896340736f;   // -SQ*log2(e)
    p.lC     = __log2f(CO);
    p.nSUB   = -p.SUB;
    p.nCRbi  = -p.CRAK * p.ivS;

    const float4* rowA = reinterpret_cast<const float4*>(in + (size_t)ba * T * 2);
    const float4* rowB = reinterpret_cast<const float4*>(in + (size_t)bb * T * 2);
    float4* outA = reinterpret_cast<float4*>(out + (size_t)ba * T);
    float4* outB = reinterpret_cast<float4*>(out + (size_t)bb * T);

    float uA = 0.f, gA = 0.f;
    float uB = 0.f, gB = 0.f;

    // peel t=0 inputs for the final Q[0] fixup
    float4 a0 = __ldg(&rowA[0]);
    float4 b0 = __ldg(&rowB[0]);
    float PrecA0 = a0.x, PETA0 = a0.y;
    float PrecB0 = b0.x, PETB0 = b0.y;

    #pragma unroll 1
    for (int i = 0; i < T / 4; ++i) {
        float4 va0 = __ldg(&rowA[2 * i]);
        float4 va1 = __ldg(&rowA[2 * i + 1]);
        float4 vb0 = __ldg(&rowB[2 * i]);
        float4 vb1 = __ldg(&rowB[2 * i + 1]);

        float4 qa, qb;
        qa.x = stepq(va0.x, va0.y, uA, gA, p);
        qb.x = stepq(vb0.x, vb0.y, uB, gB, p);
        qa.y = stepq(va0.z, va0.w, uA, gA, p);
        qb.y = stepq(vb0.z, vb0.w, uB, gB, p);
        qa.z = stepq(va1.x, va1.y, uA, gA, p);
        qb.z = stepq(vb1.x, vb1.y, uB, gB, p);
        qa.w = stepq(va1.z, va1.w, uA, gA, p);
        qb.w = stepq(vb1.z, vb1.w, uB, gB, p);

        outA[i] = qa;   // .x at i==0 is a placeholder, overwritten below
        outB[i] = qb;
    }

    // Q[0]: roll(shift=1) puts the FINAL state at t=0.
    float u2 = uA, g2 = gA;
    out[(size_t)ba * T] = stepq(PrecA0, PETA0, u2, g2, p);
    float u3 = uB, g3 = gB;
    out[(size_t)bb * T] = stepq(PrecB0, PETB0, u3, g3, p);
}

extern "C" void kernel_launch(void* const* d_in, const int* in_sizes, int n_in,
                              void* d_out, int out_size)
{
    const float* in    = (const float*)d_in[0];
    const float* INSC  = (const float*)d_in[1];
    const float* COEFF = (const float*)d_in[2];
    const float* SQ    = (const float*)d_in[3];
    const float* SMSC  = (const float*)d_in[4];
    const float* SUB   = (const float*)d_in[5];
    const float* CRAK  = (const float*)d_in[6];
    const float* RecK  = (const float*)d_in[7];
    float* out = (float*)d_out;

    constexpr int T = 1024;
    int B = out_size / T;
    int half = B >> 1;
    int blocks = (half + 31) / 32;
    hirnn_kernel<T><<<blocks, 32>>>(in, INSC, COEFF, SQ, SMSC, SUB, CRAK, RecK,
                                    out, B);
}

// round 8
// speedup vs baseline: 2.1993x; 2.1993x over previous
#include <cuda_runtime.h>
#include <cstdint>

// HIRNN (GR4J-style) forward, R8: single row per thread + register
// double-buffered input prefetch.
//
// Diagnosis history: chain ~46 cyc/step; measured 94 cyc/step. The missing
// ~48 cyc/step is DRAM latency exposed once per unroll body (loads issued at
// body top, first value consumed immediately). Fix: prefetch body i+1's
// 8 x LDG.128 at the top of body i; consume after ~740 cycles of compute,
// fully covering the ~577-cycle DRAM latency.
//
// Step identities (exact away from <=1e-6 heaviside ties):
//  - heaviside select pairs == min/max
//  - GW >= 0 by induction  =>  BAS = RecK*GW,  GW' = (1-RecK)*GW + RECn
//  - max(s-1,0) == s - min(s,1); min(s,1) feeds the u-clamp
//  - q = SUB*w + (INR-RMO) + RecK*GW as a 3-FFMA chain
//  - clip(+-1e5) provably inactive; state normalized u = SMS/SMSC in [0,1]
//
// Q[t] (t>=1) uses the pre-step state at t  -> computed inside the loop.
// Q[0] uses the FINAL state (roll shift=1)  -> recomputed after the loop.

__device__ __forceinline__ float ex2f(float x) {
    float y;
    asm("ex2.approx.f32 %0, %1;" : "=f"(y) : "f"(x));
    return y;
}

struct Params {
    float INSC, SMSC, SUB, CRAK, RecK, alpha, ivS, ck2, lC, nSUB, nCRbi;
};

__device__ __forceinline__ float stepq(float Prec, float PET,
                                       float& u, float& GW, const Params& p)
{
    float INTm = fminf(PET, Prec);
    float INT  = fminf(p.INSC, INTm);
    float INR  = Prec - INT;
    float POT  = PET - INT;

    // critical chain: FFMA -> MUFU -> FMNMX -> FFMA(s) -> clamp
    float arg = fmaf(p.ck2, u, p.lC);
    float cap = ex2f(arg);                // COEFF * exp(-SQ*u)
    float RMO = fminf(cap, INR);

    // off-chain (overlaps MUFU)
    float t10  = u * 10.0f;
    float m    = fminf(t10, POT);
    float base = fmaf(-p.ivS, m, u);      // u - ETS/SMSC
    float a    = fmaf(p.nSUB,  u, 1.0f);  // 1 - SUB*u
    float bi   = fmaf(p.nCRbi, u, p.ivS); // (1 - CRAK*u)/SMSC
    float fi   = a * bi;
    float w    = u * RMO;

    float s    = fmaf(RMO, fi, base);     // pre-clamp next u
    float umid = fminf(s, 1.0f);
    float u_n  = fmaxf(umid, 0.0f);
    float ov   = s - umid;                // == max(s-1,0)

    float cw   = p.CRAK * w;
    float REC  = cw * a;
    float RECn = fmaf(p.SMSC, ov, REC);
    float dq   = INR - RMO;
    float t1   = fmaf(p.RecK, GW, dq);    // IRUN + BAS
    float q    = fmaf(p.SUB,  w,  t1);    // + SRUN

    GW = fmaf(p.alpha, GW, RECn);         // (1-RecK)*GW + RECn
    u  = u_n;
    return q;
}

template <int T>
__global__ __launch_bounds__(32, 1)
void hirnn_kernel(const float* __restrict__ in,
                  const float* __restrict__ pINSC,
                  const float* __restrict__ pCOEFF,
                  const float* __restrict__ pSQ,
                  const float* __restrict__ pSMSC,
                  const float* __restrict__ pSUB,
                  const float* __restrict__ pCRAK,
                  const float* __restrict__ pRecK,
                  float* __restrict__ out, int B)
{
    int bidx = blockIdx.x * 32 + threadIdx.x;
    if (bidx >= B) return;

    Params p;
    p.INSC   = fminf(fmaxf(pINSC[0]  * 5.f,   0.5f),   5.f);
    float CO = fminf(fmaxf(pCOEFF[0] * 400.f, 50.f),   400.f);
    float SQ = fminf(fmaxf(pSQ[0]    * 6.f,   0.f),    6.f);
    p.SMSC   = fminf(fmaxf(pSMSC[0]  * 500.f, 50.f),   500.f);
    p.SUB    = fminf(fmaxf(pSUB[0],           0.f),    1.f);
    p.CRAK   = fminf(fmaxf(pCRAK[0],          0.f),    1.f);
    p.RecK   = fminf(fmaxf(pRecK[0]  * 0.3f,  0.003f), 0.3f);
    p.alpha  = 1.f - p.RecK;
    p.ivS    = 1.f / p.SMSC;
    p.ck2    = -SQ * 1.44269504088896340736f;   // -SQ*log2(e)
    p.lC     = __log2f(CO);
    p.nSUB   = -p.SUB;
    p.nCRbi  = -p.CRAK * p.ivS;

    const float4* row  = reinterpret_cast<const float4*>(in + (size_t)bidx * T * 2);
    float4*       orow = reinterpret_cast<float4*>(out + (size_t)bidx * T);

    // 16 timesteps per body -> 8 float4 of input, 4 float4 of output.
    constexpr int NBODY = T / 16;   // 64

    float4 buf[8];
    #pragma unroll
    for (int j = 0; j < 8; ++j) buf[j] = __ldg(&row[j]);

    float Prec0 = buf[0].x, PET0 = buf[0].y;
    float u = 0.f, GW = 0.f;

    for (int i = 0; i < NBODY; ++i) {
        // prefetch next body (last iter: reload body 0, discarded)
        int nb = (i + 1 < NBODY) ? (i + 1) * 8 : 0;
        float4 nxt[8];
        #pragma unroll
        for (int j = 0; j < 8; ++j) nxt[j] = __ldg(&row[nb + j]);

        // compute 16 steps from buf
        #pragma unroll
        for (int k = 0; k < 4; ++k) {
            float4 q;
            q.x = stepq(buf[2*k].x,   buf[2*k].y,   u, GW, p);
            q.y = stepq(buf[2*k].z,   buf[2*k].w,   u, GW, p);
            q.z = stepq(buf[2*k+1].x, buf[2*k+1].y, u, GW, p);
            q.w = stepq(buf[2*k+1].z, buf[2*k+1].w, u, GW, p);
            orow[i * 4 + k] = q;   // q.x at i==0,k==0 is a placeholder
        }

        #pragma unroll
        for (int j = 0; j < 8; ++j) buf[j] = nxt[j];
    }

    // Q[0]: roll(shift=1) puts the FINAL state at t=0.
    float u2 = u, g2 = GW;
    out[(size_t)bidx * T] = stepq(Prec0, PET0, u2, g2, p);
}

extern "C" void kernel_launch(void* const* d_in, const int* in_sizes, int n_in,
                              void* d_out, int out_size)
{
    const float* in    = (const float*)d_in[0];
    const float* INSC  = (const float*)d_in[1];
    const float* COEFF = (const float*)d_in[2];
    const float* SQ    = (const float*)d_in[3];
    const float* SMSC  = (const float*)d_in[4];
    const float* SUB   = (const float*)d_in[5];
    const float* CRAK  = (const float*)d_in[6];
    const float* RecK  = (const float*)d_in[7];
    float* out = (float*)d_out;

    constexpr int T = 1024;
    int B = out_size / T;
    int blocks = (B + 31) / 32;
    hirnn_kernel<T><<<blocks, 32>>>(in, INSC, COEFF, SQ, SMSC, SUB, CRAK, RecK,
                                    out, B);
}